// round 4
// baseline (speedup 1.0000x reference)
#include <cuda_runtime.h>

// out[b,v] = sum_c x[b,c,v] * (conv_w[c] + w_b*scale_b) + (conv_b + shift_b)
//   w_b     = silu(z[b]) . hwd_w + hwd_b
//   scale_b = silu(z[b]) . c_w[0] + c_b[0]
//   shift_b = silu(z[b]) . c_w[1] + c_b[1]
//
// B=8, C=16, 96^3 voxels. Pure HBM stream: 452 MB read + 28 MB write.
// Persistent 1-wave grid (148 SM x 8 blocks), grid-stride loop, streaming
// cache hints on both the x reads and the out writes.

#define C_CH 16
#define NV4  221184LL          // 96*96*96 / 4
#define SMS  148

__global__ __launch_bounds__(256, 8)
void fused_zprjs_conv_kernel(const float* __restrict__ x,
                             const float* __restrict__ z_prjs,
                             const float* __restrict__ conv_w,
                             const float* __restrict__ conv_b,
                             const float* __restrict__ hwd_w,
                             const float* __restrict__ hwd_b,
                             const float* __restrict__ c_w,
                             const float* __restrict__ c_b,
                             float* __restrict__ out)
{
    __shared__ float s_coef[C_CH];
    __shared__ float s_bias;

    const int b = blockIdx.y;

    if (threadIdx.x == 0) {
        const float* z = z_prjs + b * 5;
        float z0 = z[0], z1 = z[1], z2 = z[2], z3 = z[3], z4 = z[4];
        float s0 = z0 / (1.f + __expf(-z0));
        float s1 = z1 / (1.f + __expf(-z1));
        float s2 = z2 / (1.f + __expf(-z2));
        float s3 = z3 / (1.f + __expf(-z3));
        float s4 = z4 / (1.f + __expf(-z4));
        float wv = hwd_b[0] + s0 * hwd_w[0] + s1 * hwd_w[1] + s2 * hwd_w[2]
                            + s3 * hwd_w[3] + s4 * hwd_w[4];
        float sc = c_b[0] + s0 * c_w[0] + s1 * c_w[1] + s2 * c_w[2]
                          + s3 * c_w[3] + s4 * c_w[4];
        float sh = c_b[1] + s0 * c_w[5] + s1 * c_w[6] + s2 * c_w[7]
                          + s3 * c_w[8] + s4 * c_w[9];
        float a = wv * sc;
        s_bias = conv_b[0] + sh;
        #pragma unroll
        for (int c = 0; c < C_CH; c++) s_coef[c] = conv_w[c] + a;
    }
    __syncthreads();

    const float4* __restrict__ xb =
        reinterpret_cast<const float4*>(x) + (long long)b * C_CH * NV4;
    float4* __restrict__ ob =
        reinterpret_cast<float4*>(out) + (long long)b * NV4;

    const long long stride = (long long)gridDim.x * blockDim.x;
    const float bias = s_bias;

    for (long long v4 = (long long)blockIdx.x * blockDim.x + threadIdx.x;
         v4 < NV4; v4 += stride)
    {
        float4 acc = make_float4(bias, bias, bias, bias);
        #pragma unroll
        for (int c = 0; c < C_CH; c++) {
            float4 xv = __ldcs(xb + (long long)c * NV4 + v4);
            float w = s_coef[c];        // broadcast LDS, conflict-free
            acc.x = fmaf(xv.x, w, acc.x);
            acc.y = fmaf(xv.y, w, acc.y);
            acc.z = fmaf(xv.z, w, acc.z);
            acc.w = fmaf(xv.w, w, acc.w);
        }
        __stcs(ob + v4, acc);
    }
}

extern "C" void kernel_launch(void* const* d_in, const int* in_sizes, int n_in,
                              void* d_out, int out_size)
{
    const float* x      = (const float*)d_in[0];
    const float* z_prjs = (const float*)d_in[1];
    const float* conv_w = (const float*)d_in[2];
    const float* conv_b = (const float*)d_in[3];
    const float* hwd_w  = (const float*)d_in[4];
    const float* hwd_b  = (const float*)d_in[5];
    const float* c_w    = (const float*)d_in[6];
    const float* c_b    = (const float*)d_in[7];
    float* out = (float*)d_out;

    dim3 grid(SMS, 8, 1);   // 1184 blocks = 148 SMs x occ 8 -> single wave
    fused_zprjs_conv_kernel<<<grid, 256>>>(x, z_prjs, conv_w, conv_b,
                                           hwd_w, hwd_b, c_w, c_b, out);
}

// round 6
// speedup vs baseline: 1.2101x; 1.2101x over previous
#include <cuda_runtime.h>

// out[b,v] = sum_c x[b,c,v] * (conv_w[c] + w_b*scale_b) + (conv_b + shift_b)
//   w_b     = silu(z[b]) . hwd_w + hwd_b
//   scale_b = silu(z[b]) . c_w[0] + c_b[0]
//   shift_b = silu(z[b]) . c_w[1] + c_b[1]
//
// B=8, C=16, 96^3 voxels. Pure HBM stream: 452 MB read + 28 MB write.
// R1 structure (one tile per block, HW scheduler load-balances), finer
// 128-thread blocks to shrink the tail quantum, streaming store hint.

#define C_CH   16
#define NV4    221184LL        // 96*96*96 / 4
#define TPB    128

__global__ __launch_bounds__(TPB, 16)
void fused_zprjs_conv_kernel(const float* __restrict__ x,
                             const float* __restrict__ z_prjs,
                             const float* __restrict__ conv_w,
                             const float* __restrict__ conv_b,
                             const float* __restrict__ hwd_w,
                             const float* __restrict__ hwd_b,
                             const float* __restrict__ c_w,
                             const float* __restrict__ c_b,
                             float* __restrict__ out)
{
    __shared__ float s_coef[C_CH];
    __shared__ float s_bias;

    const int b = blockIdx.y;

    if (threadIdx.x == 0) {
        const float* z = z_prjs + b * 5;
        float z0 = z[0], z1 = z[1], z2 = z[2], z3 = z[3], z4 = z[4];
        float s0 = z0 / (1.f + __expf(-z0));
        float s1 = z1 / (1.f + __expf(-z1));
        float s2 = z2 / (1.f + __expf(-z2));
        float s3 = z3 / (1.f + __expf(-z3));
        float s4 = z4 / (1.f + __expf(-z4));
        float wv = hwd_b[0] + s0 * hwd_w[0] + s1 * hwd_w[1] + s2 * hwd_w[2]
                            + s3 * hwd_w[3] + s4 * hwd_w[4];
        float sc = c_b[0] + s0 * c_w[0] + s1 * c_w[1] + s2 * c_w[2]
                          + s3 * c_w[3] + s4 * c_w[4];
        float sh = c_b[1] + s0 * c_w[5] + s1 * c_w[6] + s2 * c_w[7]
                          + s3 * c_w[8] + s4 * c_w[9];
        float a = wv * sc;
        s_bias = conv_b[0] + sh;
        #pragma unroll
        for (int c = 0; c < C_CH; c++) s_coef[c] = conv_w[c] + a;
    }
    __syncthreads();

    const long long v4 = (long long)blockIdx.x * TPB + threadIdx.x;
    // NV4 = 221184 is divisible by 128 -> no bounds check needed,
    // but keep it for safety against grid rounding.
    if (v4 >= NV4) return;

    const float4* __restrict__ xb =
        reinterpret_cast<const float4*>(x) + (long long)b * C_CH * NV4 + v4;
    const float bias = s_bias;

    float4 acc = make_float4(bias, bias, bias, bias);
    #pragma unroll
    for (int c = 0; c < C_CH; c++) {
        float4 xv = __ldg(xb + (long long)c * NV4);
        float w = s_coef[c];            // broadcast LDS, conflict-free
        acc.x = fmaf(xv.x, w, acc.x);
        acc.y = fmaf(xv.y, w, acc.y);
        acc.z = fmaf(xv.z, w, acc.z);
        acc.w = fmaf(xv.w, w, acc.w);
    }

    // Streaming store: no L2 residency for the write-once output.
    __stcs(reinterpret_cast<float4*>(out) + (long long)b * NV4 + v4, acc);
}

extern "C" void kernel_launch(void* const* d_in, const int* in_sizes, int n_in,
                              void* d_out, int out_size)
{
    const float* x      = (const float*)d_in[0];
    const float* z_prjs = (const float*)d_in[1];
    const float* conv_w = (const float*)d_in[2];
    const float* conv_b = (const float*)d_in[3];
    const float* hwd_w  = (const float*)d_in[4];
    const float* hwd_b  = (const float*)d_in[5];
    const float* c_w    = (const float*)d_in[6];
    const float* c_b    = (const float*)d_in[7];
    float* out = (float*)d_out;

    dim3 grid((unsigned)((NV4 + TPB - 1) / TPB), 8, 1);   // 1728 x 8 = 13824 blocks
    fused_zprjs_conv_kernel<<<grid, TPB>>>(x, z_prjs, conv_w, conv_b,
                                           hwd_w, hwd_b, c_w, c_b, out);
}